// round 14
// baseline (speedup 1.0000x reference)
#include <cuda_runtime.h>
#include <cuda_fp16.h>
#include <math.h>
#include <stdint.h>

#define NH   8
#define NQ   2048
#define DH   64
#define CDIM 512
#define NL   64      // landmarks
#define SEG  32      // segment length (2048/64, pad = 0)
#define KL   4       // top-k landmarks

typedef unsigned long long ull;

// Scratch (device globals: no allocation allowed in kernel_launch)
__device__ float g_q[NH * NQ * DH];                    // (H, N, Dh) fp32
__device__ float g_k[NH * NQ * DH];                    // fp32 (centroids only)
__device__ __align__(16) __half g_kh[NH * NQ * DH];    // fp16 K for scores
__device__ __align__(16) __half g_vh[NH * NQ * DH];    // fp16 V for attention
__device__ float g_cent[NH * NL * DH];                 // (H, m, Dh)
__device__ float g_attn[NQ * CDIM];                    // (N, H*Dh)

// Inverted-gather structures
__device__ int   g_cnt[NH * NL];                       // routed-query counts
__device__ int   g_list[NH * NL * NQ];                 // packed (n | t<<16)
__device__ float g_pm[NH * NQ * KL];                   // per-(q,rank) max
__device__ float g_pl[NH * NQ * KL];                   // per-(q,rank) sumexp
__device__ float g_po[NH * NQ * KL * DH];              // per-(q,rank) partial out

// ---------------------------------------------------------------------------
// Packed f32x2 helpers (Blackwell FFMA2 — only reachable via PTX)
// ---------------------------------------------------------------------------
__device__ __forceinline__ ull pack2f(float lo, float hi) {
    ull r; asm("mov.b64 %0, {%1, %2};" : "=l"(r) : "f"(lo), "f"(hi)); return r;
}
__device__ __forceinline__ void unpack2f(ull v, float& lo, float& hi) {
    asm("mov.b64 {%0, %1}, %2;" : "=f"(lo), "=f"(hi) : "l"(v));
}
__device__ __forceinline__ void ffma2(ull& d, ull a, ull b) {
    asm("fma.rn.f32x2 %0, %1, %2, %3;" : "=l"(d) : "l"(a), "l"(b), "l"(d));
}
__device__ __forceinline__ unsigned pk_h2(float a, float b) {
    __half2 h = __float22half2_rn(make_float2(a, b));
    return *(unsigned*)&h;
}

// ===========================================================================
// qkv_gemm: QKV projection, rebuilt for ILP.
// C[2048,1536] = x[2048,512] @ w_qkv[1536,512]^T
// BM=128, BN=64, BK=16, 128 threads (4 warps, 2x2 warp grid, warp tile 64x32).
// Thread microtile 8x8: rows 2*tm+16*p+{0,1} (pairs along M, f32x2 acc),
// cols tn+4*j. B held in smem PRE-DUPLICATED as (b,b) f32x2 -> frag loads are
// plain LDS.64, zero per-kk packing. All frag/store patterns bank-checked.
// Epilogue scatters q/k fp32 + k/v fp16 (BN==DH: one (tensor,head) per block).
// ===========================================================================
__global__ void __launch_bounds__(128, 3) qkv_gemm(
    const float* __restrict__ A, const float* __restrict__ B)
{
    constexpr int Kd = 512, BK = 16, NK = Kd / BK;   // 32 k-tiles
    __shared__ float As[2][BK][130];   // pad 130: STS banks (2kq+arow) all distinct
    __shared__ ull   Bs[2][BK][65];    // pad 65: STS 2-way worst case, LDS clean

    const int tid = threadIdx.x, wid = tid >> 5, lane = tid & 31;
    const int warp_m = wid & 1, warp_n = wid >> 1;   // 2 x 2 warps
    const int tm = lane & 7, tn = lane >> 3;
    const int bm = blockIdx.y * 128, bn = blockIdx.x * 64;

    const int lrow = tid >> 2;            // 0..31
    const int kq = (tid & 3) * 4;
    const float* Ag = A + (size_t)(bm + lrow) * Kd + kq;
    const float* Bg = B + (size_t)(bn + lrow) * Kd + kq;

    ull acc[4][8];
    #pragma unroll
    for (int p = 0; p < 4; p++)
        #pragma unroll
        for (int j = 0; j < 8; j++) acc[p][j] = 0ull;

    float4 ra[4], rb[2];

#define G0_LOAD(kt) do {                                                       \
    _Pragma("unroll")                                                          \
    for (int r = 0; r < 4; r++) ra[r] = *(const float4*)(Ag + (size_t)(32 * r) * Kd + (kt) * BK); \
    _Pragma("unroll")                                                          \
    for (int r = 0; r < 2; r++) rb[r] = *(const float4*)(Bg + (size_t)(32 * r) * Kd + (kt) * BK); \
} while (0)

#define G0_STORE(b) do {                                                       \
    _Pragma("unroll")                                                          \
    for (int r = 0; r < 4; r++) {                                              \
        As[b][kq + 0][lrow + 32 * r] = ra[r].x;                                \
        As[b][kq + 1][lrow + 32 * r] = ra[r].y;                                \
        As[b][kq + 2][lrow + 32 * r] = ra[r].z;                                \
        As[b][kq + 3][lrow + 32 * r] = ra[r].w;                                \
    }                                                                          \
    _Pragma("unroll")                                                          \
    for (int r = 0; r < 2; r++) {                                              \
        Bs[b][kq + 0][lrow + 32 * r] = pack2f(rb[r].x, rb[r].x);               \
        Bs[b][kq + 1][lrow + 32 * r] = pack2f(rb[r].y, rb[r].y);               \
        Bs[b][kq + 2][lrow + 32 * r] = pack2f(rb[r].z, rb[r].z);               \
        Bs[b][kq + 3][lrow + 32 * r] = pack2f(rb[r].w, rb[r].w);               \
    }                                                                          \
} while (0)

#define G0_COMP(b) do {                                                        \
    _Pragma("unroll")                                                          \
    for (int kk = 0; kk < BK; kk++) {                                          \
        ull af[4], bf[8];                                                      \
        _Pragma("unroll")                                                      \
        for (int p = 0; p < 4; p++)                                            \
            af[p] = *(const ull*)&As[b][kk][warp_m * 64 + 2 * tm + 16 * p];    \
        _Pragma("unroll")                                                      \
        for (int j = 0; j < 8; j++)                                            \
            bf[j] = Bs[b][kk][warp_n * 32 + tn + 4 * j];                       \
        _Pragma("unroll")                                                      \
        for (int p = 0; p < 4; p++)                                            \
            _Pragma("unroll")                                                  \
            for (int j = 0; j < 8; j++)                                        \
                ffma2(acc[p][j], af[p], bf[j]);                                \
    }                                                                          \
} while (0)

    G0_LOAD(0);
    G0_STORE(0);
    __syncthreads();

    for (int kt = 0; kt < NK; kt++) {
        const int buf = kt & 1;
        if (kt + 1 < NK) G0_LOAD(kt + 1);
        G0_COMP(buf);
        if (kt + 1 < NK) {
            G0_STORE(buf ^ 1);
            __syncthreads();
        }
    }

    // ---- epilogue: scatter into (H,N,Dh) q/k fp32 + k/v fp16 ----
    const int t = bn >> 9;            // 0=q, 1=k, 2=v  (BN == DH == 64)
    const int h = (bn >> 6) & 7;
    #pragma unroll
    for (int p = 0; p < 4; p++) {
        float lo[8], hi[8];
        #pragma unroll
        for (int j = 0; j < 8; j++) unpack2f(acc[p][j], lo[j], hi[j]);
        const int r0 = bm + warp_m * 64 + 2 * tm + 16 * p;
        #pragma unroll
        for (int s = 0; s < 2; s++) {
            const float* vals = s ? hi : lo;
            const size_t base = ((size_t)h * NQ + r0 + s) * DH + warp_n * 32 + tn;
            if (t == 0) {
                #pragma unroll
                for (int j = 0; j < 8; j++) g_q[base + 4 * j] = vals[j];
            } else if (t == 1) {
                #pragma unroll
                for (int j = 0; j < 8; j++) {
                    g_k[base + 4 * j] = vals[j];
                    g_kh[base + 4 * j] = __float2half_rn(vals[j]);
                }
            } else {
                #pragma unroll
                for (int j = 0; j < 8; j++) g_vh[base + 4 * j] = __float2half_rn(vals[j]);
            }
        }
    }
#undef G0_LOAD
#undef G0_STORE
#undef G0_COMP
}

// ===========================================================================
// f32x2 GEMM (R13-proven) — used for the output projection only.
// ===========================================================================
template <int MODE>
__global__ void __launch_bounds__(256) gemm_kernel(
    const float* __restrict__ A, const float* __restrict__ B,
    const float* __restrict__ bias, float* __restrict__ Cout)
{
    constexpr int Kd = 512, BK = 16, NK = Kd / BK;
    __shared__ __align__(16) float As[2][BK][128 + 4];
    __shared__ __align__(16) float Bs[2][BK][64 + 4];

    const float* Aptr = (MODE == 1) ? (const float*)g_attn : A;
    const int tid = threadIdx.x;
    const int bm = blockIdx.y * 128, bn = blockIdx.x * 64;
    const int tx = tid & 15, ty = tid >> 4;
    const int lrow = tid >> 2, kq = (tid & 3) * 4;

    const float* Ag0 = Aptr + (size_t)(bm + lrow) * Kd + kq;
    const float* Ag1 = Ag0 + (size_t)64 * Kd;
    const float* Bg  = B + (size_t)(bn + lrow) * Kd + kq;

    ull acc[4][4];
    #pragma unroll
    for (int p = 0; p < 4; p++)
        #pragma unroll
        for (int j = 0; j < 4; j++) acc[p][j] = 0ull;

    float4 ra0, ra1, rb;

#define STORE_TILE(b) do {                                                     \
    As[b][kq+0][lrow]    = ra0.x; As[b][kq+1][lrow]    = ra0.y;                \
    As[b][kq+2][lrow]    = ra0.z; As[b][kq+3][lrow]    = ra0.w;                \
    As[b][kq+0][lrow+64] = ra1.x; As[b][kq+1][lrow+64] = ra1.y;                \
    As[b][kq+2][lrow+64] = ra1.z; As[b][kq+3][lrow+64] = ra1.w;                \
    Bs[b][kq+0][lrow]    = rb.x;  Bs[b][kq+1][lrow]    = rb.y;                 \
    Bs[b][kq+2][lrow]    = rb.z;  Bs[b][kq+3][lrow]    = rb.w;                 \
} while (0)

#define COMP_TILE(b) do {                                                      \
    _Pragma("unroll")                                                          \
    for (int kk = 0; kk < BK; kk++) {                                          \
        const float* Ak = &As[b][kk][ty * 8];                                  \
        ull a01 = *(const ull*)(Ak + 0), a23 = *(const ull*)(Ak + 2);          \
        ull a45 = *(const ull*)(Ak + 4), a67 = *(const ull*)(Ak + 6);          \
        float4 bv = *(const float4*)&Bs[b][kk][tx * 4];                        \
        ull b0 = pack2f(bv.x, bv.x), b1 = pack2f(bv.y, bv.y);                  \
        ull b2 = pack2f(bv.z, bv.z), b3 = pack2f(bv.w, bv.w);                  \
        ffma2(acc[0][0], a01, b0); ffma2(acc[0][1], a01, b1);                  \
        ffma2(acc[0][2], a01, b2); ffma2(acc[0][3], a01, b3);                  \
        ffma2(acc[1][0], a23, b0); ffma2(acc[1][1], a23, b1);                  \
        ffma2(acc[1][2], a23, b2); ffma2(acc[1][3], a23, b3);                  \
        ffma2(acc[2][0], a45, b0); ffma2(acc[2][1], a45, b1);                  \
        ffma2(acc[2][2], a45, b2); ffma2(acc[2][3], a45, b3);                  \
        ffma2(acc[3][0], a67, b0); ffma2(acc[3][1], a67, b1);                  \
        ffma2(acc[3][2], a67, b2); ffma2(acc[3][3], a67, b3);                  \
    }                                                                          \
} while (0)

    ra0 = *(const float4*)Ag0; ra1 = *(const float4*)Ag1; rb = *(const float4*)Bg;
    STORE_TILE(0);
    __syncthreads();

    for (int kt = 0; kt < NK; kt++) {
        const int buf = kt & 1;
        if (kt + 1 < NK) {
            ra0 = *(const float4*)(Ag0 + (kt + 1) * BK);
            ra1 = *(const float4*)(Ag1 + (kt + 1) * BK);
            rb  = *(const float4*)(Bg  + (kt + 1) * BK);
        }
        COMP_TILE(buf);
        if (kt + 1 < NK) {
            STORE_TILE(buf ^ 1);
            __syncthreads();
        }
    }

    {
        float4 bv = *(const float4*)(bias + bn + tx * 4);
        #pragma unroll
        for (int p = 0; p < 4; p++) {
            float lo0, hi0, lo1, hi1, lo2, hi2, lo3, hi3;
            unpack2f(acc[p][0], lo0, hi0); unpack2f(acc[p][1], lo1, hi1);
            unpack2f(acc[p][2], lo2, hi2); unpack2f(acc[p][3], lo3, hi3);
            const int r = bm + ty * 8 + p * 2;
            float* rp = Cout + (size_t)r * CDIM + bn + tx * 4;
            *(float4*)rp = make_float4(lo0 + bv.x, lo1 + bv.y, lo2 + bv.z, lo3 + bv.w);
            *(float4*)(rp + CDIM) = make_float4(hi0 + bv.x, hi1 + bv.y, hi2 + bv.z, hi3 + bv.w);
        }
    }
#undef STORE_TILE
#undef COMP_TILE
}

// ---------------------------------------------------------------------------
// Centroids: mean of each 32-row K segment (fp32 K).
// ---------------------------------------------------------------------------
__global__ void __launch_bounds__(64) centroid_kernel()
{
    const int hm = blockIdx.x;
    const int d = threadIdx.x;
    const float* kp = g_k + (size_t)hm * SEG * DH + d;
    float s = 0.f;
    #pragma unroll
    for (int r = 0; r < SEG; r++) s += kp[r * DH];
    g_cent[(size_t)hm * DH + d] = s * (1.0f / SEG);
}

// ---------------------------------------------------------------------------
// Zero the routing counters (runs every replay — graph determinism).
// ---------------------------------------------------------------------------
__global__ void __launch_bounds__(512) zero_kernel()
{
    g_cnt[threadIdx.x] = 0;
}

// ---------------------------------------------------------------------------
// Routing v3: one thread per query, 64-thread blocks, grid = NH * NQ/64 = 256
// (R13 had grid 64 -> <half the chip active; this is the occupancy fix).
// ---------------------------------------------------------------------------
__global__ void __launch_bounds__(64) route_kernel()
{
    __shared__ __align__(16) float cs[NL][DH];   // 16 KB, broadcast reads only

    const int tid = threadIdx.x;
    const int h = blockIdx.x >> 5;
    const int n = (blockIdx.x & 31) * 64 + tid;

    // stage centroid table (1024 float4, 16 per thread)
    {
        const float4* src = (const float4*)(g_cent + (size_t)h * NL * DH);
        float4* dst = (float4*)&cs[0][0];
        #pragma unroll
        for (int i = 0; i < 16; i++) dst[tid + i * 64] = src[tid + i * 64];
    }
    __syncthreads();

    // q row -> 32 packed f32x2 registers
    ull q2[DH / 2];
    {
        const float4* qp = (const float4*)(g_q + ((size_t)h * NQ + n) * DH);
        #pragma unroll
        for (int i = 0; i < DH / 4; i++) {
            float4 v = qp[i];
            q2[2 * i]     = pack2f(v.x, v.y);
            q2[2 * i + 1] = pack2f(v.z, v.w);
        }
    }

    float tv0 = -INFINITY, tv1 = -INFINITY, tv2 = -INFINITY, tv3 = -INFINITY;
    int   ti0 = 0, ti1 = 0, ti2 = 0, ti3 = 0;

    #pragma unroll 4
    for (int m = 0; m < NL; m++) {
        ull a0 = 0ull, a1 = 0ull, a2 = 0ull, a3 = 0ull;
        const float4* cp = (const float4*)&cs[m][0];
        #pragma unroll
        for (int i = 0; i < DH / 8; i++) {
            float4 c0 = cp[2 * i], c1 = cp[2 * i + 1];   // LDS.128 broadcast
            ffma2(a0, q2[4 * i],     pack2f(c0.x, c0.y));
            ffma2(a1, q2[4 * i + 1], pack2f(c0.z, c0.w));
            ffma2(a2, q2[4 * i + 2], pack2f(c1.x, c1.y));
            ffma2(a3, q2[4 * i + 3], pack2f(c1.z, c1.w));
        }
        float x0, y0, x1, y1, x2, y2, x3, y3;
        unpack2f(a0, x0, y0); unpack2f(a1, x1, y1);
        unpack2f(a2, x2, y2); unpack2f(a3, x3, y3);
        const float s = ((x0 + y0) + (x1 + y1)) + ((x2 + y2) + (x3 + y3));

        // streaming top-4 insert (strict >: earlier m wins ties, matching jax)
        if (s > tv3) {
            if (s > tv2) {
                tv3 = tv2; ti3 = ti2;
                if (s > tv1) {
                    tv2 = tv1; ti2 = ti1;
                    if (s > tv0) { tv1 = tv0; ti1 = ti0; tv0 = s; ti0 = m; }
                    else         { tv1 = s; ti1 = m; }
                } else { tv2 = s; ti2 = m; }
            } else { tv3 = s; ti3 = m; }
        }
    }

    int slot;
    slot = atomicAdd(&g_cnt[h * NL + ti0], 1);
    g_list[(size_t)(h * NL + ti0) * NQ + slot] = n;
    slot = atomicAdd(&g_cnt[h * NL + ti1], 1);
    g_list[(size_t)(h * NL + ti1) * NQ + slot] = n | (1 << 16);
    slot = atomicAdd(&g_cnt[h * NL + ti2], 1);
    g_list[(size_t)(h * NL + ti2) * NQ + slot] = n | (2 << 16);
    slot = atomicAdd(&g_cnt[h * NL + ti3], 1);
    g_list[(size_t)(h * NL + ti3) * NQ + slot] = n | (3 << 16);
}

// ---------------------------------------------------------------------------
// Phase A: one block per (h, landmark). K/V segment staged in smem once;
// each warp holds key row `lane` in registers and streams routed queries,
// writing flash-style partials (m, l, o[64]) indexed by (h, n, rank).
// ---------------------------------------------------------------------------
__global__ void __launch_bounds__(256) seg_attn_kernel()
{
    __shared__ __half ks[SEG][DH + 2];
    __shared__ __half2 vs[SEG][DH / 2];
    __shared__ float sq[8][64];
    __shared__ float sp[8][SEG];
    __shared__ int s_cnt;

    const int tid = threadIdx.x, warp = tid >> 5, lane = tid & 31;
    const int hm = blockIdx.x;           // h*NL + m
    const int h = hm >> 6;
    const float scale = 0.125f;

    const size_t seg_base = (size_t)hm * SEG * DH;
    for (int i = tid; i < SEG * DH; i += 256) {
        int r = i >> 6, c = i & 63;
        ks[r][c] = g_kh[seg_base + i];
        ((__half*)&vs[r][0])[c] = g_vh[seg_base + i];
    }
    if (tid == 0) s_cnt = g_cnt[hm];
    __syncthreads();

    __half2 kreg[DH / 2];
    #pragma unroll
    for (int c = 0; c < DH / 2; c++)
        kreg[c] = *(const __half2*)&ks[lane][2 * c];

    const int cnt = s_cnt;
    const int* list = g_list + (size_t)hm * NQ;

    for (int i = warp; i < cnt; i += 8) {
        const int e = list[i];
        const int n = e & 0xffff, t = e >> 16;

        const float* qp = g_q + ((size_t)h * NQ + n) * DH;
        sq[warp][lane] = qp[lane];
        sq[warp][lane + 32] = qp[lane + 32];
        __syncwarp();

        float s = 0.f;
        #pragma unroll
        for (int c = 0; c < DH / 2; c++) {
            float2 kf = __half22float2(kreg[c]);
            s += sq[warp][2 * c] * kf.x + sq[warp][2 * c + 1] * kf.y;
        }
        s *= scale;

        float mx = s;
        #pragma unroll
        for (int o = 16; o; o >>= 1) mx = fmaxf(mx, __shfl_xor_sync(0xffffffffu, mx, o));
        float p = __expf(s - mx);
        float l = p;
        #pragma unroll
        for (int o = 16; o; o >>= 1) l += __shfl_xor_sync(0xffffffffu, l, o);

        sp[warp][lane] = p;
        __syncwarp();

        float ax = 0.f, ay = 0.f;
        #pragma unroll
        for (int j = 0; j < SEG; j++) {
            float pj = sp[warp][j];
            float2 v = __half22float2(vs[j][lane]);
            ax += pj * v.x; ay += pj * v.y;
        }

        const size_t pb = ((size_t)h * NQ + n) * KL + t;
        *(float2*)(g_po + pb * DH + 2 * lane) = make_float2(ax, ay);
        if (lane == 0) { g_pm[pb] = mx; g_pl[pb] = l; }
        __syncwarp();
    }
}

// ---------------------------------------------------------------------------
// Combine: merge the 4 rank partials per query (exact two-level softmax).
// ---------------------------------------------------------------------------
__global__ void __launch_bounds__(256) combine_kernel()
{
    const int warp = threadIdx.x >> 5, lane = threadIdx.x & 31;
    const int gw = blockIdx.x * 8 + warp;
    const int h = gw >> 11;
    const int n = gw & (NQ - 1);

    const size_t pb = ((size_t)h * NQ + n) * KL;

    float m0 = g_pm[pb + 0], m1 = g_pm[pb + 1], m2 = g_pm[pb + 2], m3 = g_pm[pb + 3];
    float l0 = g_pl[pb + 0], l1 = g_pl[pb + 1], l2 = g_pl[pb + 2], l3 = g_pl[pb + 3];
    const float M = fmaxf(fmaxf(m0, m1), fmaxf(m2, m3));
    const float w0 = __expf(m0 - M), w1 = __expf(m1 - M);
    const float w2 = __expf(m2 - M), w3 = __expf(m3 - M);
    const float inv = 1.0f / (l0 * w0 + l1 * w1 + l2 * w2 + l3 * w3);

    float2 o0 = *(const float2*)(g_po + (pb + 0) * DH + 2 * lane);
    float2 o1 = *(const float2*)(g_po + (pb + 1) * DH + 2 * lane);
    float2 o2 = *(const float2*)(g_po + (pb + 2) * DH + 2 * lane);
    float2 o3 = *(const float2*)(g_po + (pb + 3) * DH + 2 * lane);

    float ax = w0 * o0.x + w1 * o1.x + w2 * o2.x + w3 * o3.x;
    float ay = w0 * o0.y + w1 * o1.y + w2 * o2.y + w3 * o3.y;

    float* op = g_attn + (size_t)n * CDIM + h * DH + 2 * lane;
    *(float2*)op = make_float2(ax * inv, ay * inv);
}

// ---------------------------------------------------------------------------
extern "C" void kernel_launch(void* const* d_in, const int* in_sizes, int n_in,
                              void* d_out, int out_size)
{
    const float* x      = (const float*)d_in[0];   // (1, 2048, 512)
    const float* w_qkv  = (const float*)d_in[1];   // (1536, 512)
    const float* w_proj = (const float*)d_in[2];   // (512, 512)
    const float* b_proj = (const float*)d_in[3];   // (512,)
    float* out = (float*)d_out;                    // (1, 2048, 512)

    // 1) QKV GEMM (rebuilt: 8x8 microtile, pre-duplicated B, 384x128thr)
    qkv_gemm<<<dim3(3 * CDIM / 64, NQ / 128), 128>>>(x, w_qkv);
    // 2) Landmark centroids (fp32)
    centroid_kernel<<<NH * NL, 64>>>();
    // 3) Routing v3: full-chip grid
    zero_kernel<<<1, 512>>>();
    route_kernel<<<NH * NQ / 64, 64>>>();
    // 4) Phase A: per-(h,landmark) segment attention -> partials
    seg_attn_kernel<<<NH * NL, 256>>>();
    // 5) Combine partials (exact softmax merge)
    combine_kernel<<<NH * NQ / 8, 256>>>();
    // 6) Output projection + bias (f32x2)
    gemm_kernel<1><<<dim3(CDIM / 64, NQ / 128), 256>>>(nullptr, w_proj, b_proj, out);
}